// round 11
// baseline (speedup 1.0000x reference)
#include <cuda_runtime.h>
#include <cuda_bf16.h>
#include <cstdint>

#define N_NODES 40000
#define E_EDGES 640000
#define R_REL   8
#define H_DIM   128
#define C_DIM   64
#define TILES   313          // ceil(40000/128)
#define ROWS_PAD (TILES * 128)
#define CNT_BLKS 2500        // E/256
#define W2P_BLKS 144         // 9*64*64/256
#define SCAN_BLKS 40

// ---------------- scratch (device globals; no allocation) ----------------
__device__ int                g_cnt_rel[N_NODES * R_REL];
__device__ int                g_off[N_NODES + 1];
__device__ int                g_cursor[N_NODES];
__device__ volatile int       g_scan_state[SCAN_BLKS];   // 0 none, 1 agg, 2 prefix
__device__ volatile int       g_scan_agg[SCAN_BLKS];
__device__ volatile int       g_scan_pfx[SCAN_BLKS];
__device__ unsigned long long g_edge[E_EDGES];           // (scale<<32 | rowid) sorted by dst
__device__ float              g_hall[(size_t)R_REL * N_NODES * C_DIM];
// bf16 split images of h (A operand), row-major [row][k], packed bf16x2 words
__device__ __align__(16) uint32_t g_Ahi[(size_t)ROWS_PAD * 64];
__device__ __align__(16) uint32_t g_Alo[(size_t)ROWS_PAD * 64];
// bf16 split images of W2[r]/root2 (B operand), [r][col][k] packed bf16x2 words
__device__ __align__(16) uint32_t g_Bhi[9 * 64 * 64];
__device__ __align__(16) uint32_t g_Blo[9 * 64 * 64];

// ---------------- helpers ----------------
__device__ __forceinline__ uint32_t pk_hi2(float a, float b, float& la, float& lb) {
    __nv_bfloat16 ha = __float2bfloat16(a);
    __nv_bfloat16 hb = __float2bfloat16(b);
    la = a - __bfloat162float(ha);
    lb = b - __bfloat162float(hb);
    __nv_bfloat162 t(ha, hb);            // ha -> low half
    return *reinterpret_cast<uint32_t*>(&t);
}
__device__ __forceinline__ uint32_t pk2(float a, float b) {
    __nv_bfloat162 t = __floats2bfloat162_rn(a, b);   // a -> low half
    return *reinterpret_cast<uint32_t*>(&t);
}
__device__ __forceinline__ void mma16816(float* c, const uint32_t* a, const uint32_t* b) {
    asm volatile(
        "mma.sync.aligned.m16n8k16.row.col.f32.bf16.bf16.f32 "
        "{%0,%1,%2,%3}, {%4,%5,%6,%7}, {%8,%9}, {%0,%1,%2,%3};"
        : "+f"(c[0]), "+f"(c[1]), "+f"(c[2]), "+f"(c[3])
        : "r"(a[0]), "r"(a[1]), "r"(a[2]), "r"(a[3]), "r"(b[0]), "r"(b[1]));
}
__device__ __forceinline__ int warp_incl_scan(int v, int lane) {
#pragma unroll
    for (int ofs = 1; ofs < 32; ofs <<= 1) {
        int u = __shfl_up_sync(0xffffffffu, v, ofs);
        if (lane >= ofs) v += u;
    }
    return v;
}

// ---------------- count (+ fused w2prep + scan-state reset) ------------------
__global__ void count_kernel(const int* __restrict__ edge_index,
                             const int* __restrict__ edge_type,
                             const float* __restrict__ W2,
                             const float* __restrict__ root2) {
    if (blockIdx.x < CNT_BLKS) {
        int e = blockIdx.x * 256 + threadIdx.x;
        if (blockIdx.x == 0 && threadIdx.x < SCAN_BLKS)
            g_scan_state[threadIdx.x] = 0;            // reset lookback flags
        if (e < E_EDGES) {
            int dst = edge_index[E_EDGES + e];
            int et  = edge_type[e];
            atomicAdd(&g_cnt_rel[dst * R_REL + et], 1);
        }
    } else {
        // ---- w2prep: W2[r]/root2 -> [r][col][k] bf16 hi/lo ----
        int idx = (blockIdx.x - CNT_BLKS) * 256 + threadIdx.x;
        if (idx >= 9 * 64 * 64) return;
        int r   = idx >> 12;
        int rem = idx & 4095;
        int n   = rem >> 6;
        int k   = (rem & 63) * 2;
        const float* mat = (r < 8) ? (W2 + (size_t)r * H_DIM * C_DIM) : root2;
        float x0 = mat[(size_t)k * C_DIM + n];
        float x1 = mat[(size_t)(k + 1) * C_DIM + n];
        float l0, l1;
        uint32_t hi = pk_hi2(x0, x1, l0, l1);
        uint32_t lo = pk2(l0, l1);
        g_Bhi[idx] = hi;
        g_Blo[idx] = lo;
    }
}

// ---------------- single-kernel scan (warp shuffles + decoupled lookback) ----
__global__ __launch_bounds__(1024) void scan_kernel() {
    const int b = blockIdx.x, t = threadIdx.x;
    const int lane = t & 31, warp = t >> 5;
    int i = b * 1024 + t;
    int deg = 0;
    if (i < N_NODES) {
        const int4* p = reinterpret_cast<const int4*>(&g_cnt_rel[i * R_REL]);
        int4 a = p[0], c = p[1];
        deg = a.x + a.y + a.z + a.w + c.x + c.y + c.z + c.w;
    }
    int v = warp_incl_scan(deg, lane);
    __shared__ int ws[32];
    __shared__ int s_prefix;
    if (lane == 31) ws[warp] = v;
    __syncthreads();
    if (warp == 0) {
        int w = ws[lane];
        w = warp_incl_scan(w, lane);
        ws[lane] = w;
    }
    __syncthreads();
    int blockExcl = warp ? ws[warp - 1] : 0;
    int incl  = blockExcl + v;          // inclusive within block
    int total = ws[31];

    if (t == 0) {
        g_scan_agg[b] = total;
        __threadfence();
        g_scan_state[b] = 1;
        int pfx = 0;
        for (int p = b - 1; p >= 0; ) {
            int st;
            do { st = g_scan_state[p]; } while (st == 0);
            __threadfence();
            if (st == 2) { pfx += g_scan_pfx[p]; break; }
            pfx += g_scan_agg[p];
            p--;
        }
        g_scan_pfx[b] = pfx + total;
        __threadfence();
        g_scan_state[b] = 2;
        s_prefix = pfx;
    }
    __syncthreads();
    int off = s_prefix + incl - deg;
    if (i < N_NODES) {
        g_off[i]    = off;
        g_cursor[i] = off;
    }
    if (i == 0) g_off[N_NODES] = E_EDGES;
}

__global__ void permute_kernel(const int* __restrict__ edge_index,
                               const int* __restrict__ edge_type) {
    int e = blockIdx.x * blockDim.x + threadIdx.x;
    if (e >= E_EDGES) return;
    int src = edge_index[e];
    int dst = edge_index[E_EDGES + e];
    int et  = edge_type[e];
    int pos = atomicAdd(&g_cursor[dst], 1);
    int cnt = g_cnt_rel[dst * R_REL + et];
    float sc = 1.0f / (float)cnt;
    unsigned rowid = (unsigned)(et * N_NODES + src);
    g_edge[pos] = ((unsigned long long)__float_as_uint(sc) << 32) | rowid;
}

// ---------------- layer 1 aggregation: warp per node, 8-deep prefetch --------
__global__ __launch_bounds__(256) void agg1_kernel(const float* __restrict__ W1,
                                                   const float* __restrict__ root1,
                                                   const float* __restrict__ b1) {
    int wid  = threadIdx.x >> 5;
    int lane = threadIdx.x & 31;
    int n = blockIdx.x * 8 + wid;
    if (n >= N_NODES) return;
    int beg = g_off[n], end = g_off[n + 1];

    float4 acc0 = make_float4(0.f, 0.f, 0.f, 0.f);
    float4 acc1 = make_float4(0.f, 0.f, 0.f, 0.f);
    for (int base = beg; base < end; base += 32) {
        int e = base + lane;
        unsigned long long pk = (e < end) ? g_edge[e] : 0ull;
        int m = end - base; if (m > 32) m = 32;
        for (int j0 = 0; j0 < m; j0 += 8) {
            int c = m - j0; if (c > 8) c = 8;
            float s[8]; float4 v[8];
#pragma unroll
            for (int q = 0; q < 8; q++) {
                unsigned long long pj = __shfl_sync(0xffffffffu, pk, j0 + q);
                if (q < c) {
                    s[q] = __uint_as_float((unsigned)(pj >> 32));
                    v[q] = *reinterpret_cast<const float4*>(
                        &W1[(size_t)(unsigned)(pj & 0xffffffffu) * H_DIM + lane * 4]);
                } else {
                    s[q] = 0.f;
                    v[q] = make_float4(0.f, 0.f, 0.f, 0.f);
                }
            }
#pragma unroll
            for (int q = 0; q < 8; q += 2) {
                acc0.x = fmaf(s[q], v[q].x, acc0.x);
                acc0.y = fmaf(s[q], v[q].y, acc0.y);
                acc0.z = fmaf(s[q], v[q].z, acc0.z);
                acc0.w = fmaf(s[q], v[q].w, acc0.w);
                acc1.x = fmaf(s[q + 1], v[q + 1].x, acc1.x);
                acc1.y = fmaf(s[q + 1], v[q + 1].y, acc1.y);
                acc1.z = fmaf(s[q + 1], v[q + 1].z, acc1.z);
                acc1.w = fmaf(s[q + 1], v[q + 1].w, acc1.w);
            }
        }
    }
    float4 rt = *reinterpret_cast<const float4*>(&root1[(size_t)n * H_DIM + lane * 4]);
    float4 bb = *reinterpret_cast<const float4*>(&b1[lane * 4]);
    float4 o;
    o.x = fmaxf(acc0.x + acc1.x + rt.x + bb.x, 0.f);
    o.y = fmaxf(acc0.y + acc1.y + rt.y + bb.y, 0.f);
    o.z = fmaxf(acc0.z + acc1.z + rt.z + bb.z, 0.f);
    o.w = fmaxf(acc0.w + acc1.w + rt.w + bb.w, 0.f);

    float l0, l1, l2, l3;
    uint32_t h01 = pk_hi2(o.x, o.y, l0, l1);
    uint32_t h23 = pk_hi2(o.z, o.w, l2, l3);
    uint32_t w01 = pk2(l0, l1);
    uint32_t w23 = pk2(l2, l3);
    size_t base = (size_t)n * 64 + lane * 2;
    g_Ahi[base]     = h01;
    g_Ahi[base + 1] = h23;
    g_Alo[base]     = w01;
    g_Alo[base + 1] = w23;
}

// ---------------- bf16-split HMMA batched GEMM -------------------------------
#define ROW_B   272
#define A_HI_O  0
#define A_LO_O  34816
#define B_HI_O  69632
#define B_LO_O  87040
#define SM_TOT  104448

__global__ __launch_bounds__(256) void gemm_kernel(const float* __restrict__ bias2,
                                                   float* __restrict__ out) {
    extern __shared__ char sm[];
    const int tid    = threadIdx.x;
    const int lane   = tid & 31;
    const int wid    = tid >> 5;
    const int warp_m = wid >> 1;
    const int warp_n = wid & 1;
    const int g      = lane >> 2;
    const int t      = lane & 3;
    const int tile   = blockIdx.x;

    {
        const float4* sH = reinterpret_cast<const float4*>(g_Ahi + (size_t)tile * 128 * 64);
        const float4* sL = reinterpret_cast<const float4*>(g_Alo + (size_t)tile * 128 * 64);
#pragma unroll
        for (int i = 0; i < 8; i++) {
            int f    = tid + 256 * i;
            int row  = f >> 4;
            int ch   = f & 15;
            *reinterpret_cast<float4*>(sm + A_HI_O + row * ROW_B + ch * 16) = sH[f];
            *reinterpret_cast<float4*>(sm + A_LO_O + row * ROW_B + ch * 16) = sL[f];
        }
    }

    for (int r = 0; r < 9; r++) {
        {
            const float4* sH = reinterpret_cast<const float4*>(g_Bhi + r * 4096);
            const float4* sL = reinterpret_cast<const float4*>(g_Blo + r * 4096);
#pragma unroll
            for (int i = 0; i < 4; i++) {
                int f   = tid + 256 * i;
                int col = f >> 4;
                int ch  = f & 15;
                *reinterpret_cast<float4*>(sm + B_HI_O + col * ROW_B + ch * 16) = sH[f];
                *reinterpret_cast<float4*>(sm + B_LO_O + col * ROW_B + ch * 16) = sL[f];
            }
        }
        __syncthreads();

        float acc[2][4][4];
#pragma unroll
        for (int m = 0; m < 2; m++)
#pragma unroll
            for (int n = 0; n < 4; n++)
#pragma unroll
                for (int c = 0; c < 4; c++) acc[m][n][c] = 0.f;

#pragma unroll
        for (int k8 = 0; k8 < 8; k8++) {
            const int kbyte = (k8 * 16 + t * 2) * 2;
            uint32_t ahi[2][4], alo[2][4];
#pragma unroll
            for (int m = 0; m < 2; m++) {
                const char* p = sm + (warp_m * 32 + m * 16 + g) * ROW_B + kbyte;
                ahi[m][0] = *(const uint32_t*)(p + A_HI_O);
                ahi[m][1] = *(const uint32_t*)(p + A_HI_O + 8 * ROW_B);
                ahi[m][2] = *(const uint32_t*)(p + A_HI_O + 16);
                ahi[m][3] = *(const uint32_t*)(p + A_HI_O + 8 * ROW_B + 16);
                alo[m][0] = *(const uint32_t*)(p + A_LO_O);
                alo[m][1] = *(const uint32_t*)(p + A_LO_O + 8 * ROW_B);
                alo[m][2] = *(const uint32_t*)(p + A_LO_O + 16);
                alo[m][3] = *(const uint32_t*)(p + A_LO_O + 8 * ROW_B + 16);
            }
            uint32_t bhi[4][2], blo[4][2];
#pragma unroll
            for (int n = 0; n < 4; n++) {
                const char* p = sm + (warp_n * 32 + n * 8 + g) * ROW_B + kbyte;
                bhi[n][0] = *(const uint32_t*)(p + B_HI_O);
                bhi[n][1] = *(const uint32_t*)(p + B_HI_O + 16);
                blo[n][0] = *(const uint32_t*)(p + B_LO_O);
                blo[n][1] = *(const uint32_t*)(p + B_LO_O + 16);
            }
#pragma unroll
            for (int m = 0; m < 2; m++)
#pragma unroll
                for (int n = 0; n < 4; n++) {
                    mma16816(acc[m][n], ahi[m], bhi[n]);
                    mma16816(acc[m][n], ahi[m], blo[n]);
                    mma16816(acc[m][n], alo[m], bhi[n]);
                }
        }
        __syncthreads();

#pragma unroll
        for (int m = 0; m < 2; m++) {
            int row0 = tile * 128 + warp_m * 32 + m * 16 + g;
#pragma unroll
            for (int n = 0; n < 4; n++) {
                int col = warp_n * 32 + n * 8 + t * 2;
                if (r < 8) {
                    float* baseP = &g_hall[(size_t)r * N_NODES * C_DIM];
                    if (row0 < N_NODES)
                        *reinterpret_cast<float2*>(&baseP[(size_t)row0 * C_DIM + col]) =
                            make_float2(acc[m][n][0], acc[m][n][1]);
                    if (row0 + 8 < N_NODES)
                        *reinterpret_cast<float2*>(&baseP[(size_t)(row0 + 8) * C_DIM + col]) =
                            make_float2(acc[m][n][2], acc[m][n][3]);
                } else {
                    float2 bb = *reinterpret_cast<const float2*>(&bias2[col]);
                    if (row0 < N_NODES)
                        *reinterpret_cast<float2*>(&out[(size_t)row0 * C_DIM + col]) =
                            make_float2(acc[m][n][0] + bb.x, acc[m][n][1] + bb.y);
                    if (row0 + 8 < N_NODES)
                        *reinterpret_cast<float2*>(&out[(size_t)(row0 + 8) * C_DIM + col]) =
                            make_float2(acc[m][n][2] + bb.x, acc[m][n][3] + bb.y);
                }
            }
        }
    }
}

// ---------------- layer 2 aggregation: warp per node, 8-deep prefetch --------
__global__ __launch_bounds__(256) void agg2_kernel(float* __restrict__ out) {
    int wid  = threadIdx.x >> 5;
    int lane = threadIdx.x & 31;
    int n = blockIdx.x * 8 + wid;
    if (n >= N_NODES) return;
    int beg = g_off[n], end = g_off[n + 1];
    if (beg == end) return;

    float2 acc0 = make_float2(0.f, 0.f);
    float2 acc1 = make_float2(0.f, 0.f);
    for (int base = beg; base < end; base += 32) {
        int e = base + lane;
        unsigned long long pk = (e < end) ? g_edge[e] : 0ull;
        int m = end - base; if (m > 32) m = 32;
        for (int j0 = 0; j0 < m; j0 += 8) {
            int c = m - j0; if (c > 8) c = 8;
            float s[8]; float2 v[8];
#pragma unroll
            for (int q = 0; q < 8; q++) {
                unsigned long long pj = __shfl_sync(0xffffffffu, pk, j0 + q);
                if (q < c) {
                    s[q] = __uint_as_float((unsigned)(pj >> 32));
                    v[q] = *reinterpret_cast<const float2*>(
                        &g_hall[(size_t)(unsigned)(pj & 0xffffffffu) * C_DIM + lane * 2]);
                } else {
                    s[q] = 0.f;
                    v[q] = make_float2(0.f, 0.f);
                }
            }
#pragma unroll
            for (int q = 0; q < 8; q += 2) {
                acc0.x = fmaf(s[q], v[q].x, acc0.x);
                acc0.y = fmaf(s[q], v[q].y, acc0.y);
                acc1.x = fmaf(s[q + 1], v[q + 1].x, acc1.x);
                acc1.y = fmaf(s[q + 1], v[q + 1].y, acc1.y);
            }
        }
    }
    float2* po = reinterpret_cast<float2*>(&out[(size_t)n * C_DIM + lane * 2]);
    float2 cur = *po;
    cur.x += acc0.x + acc1.x;
    cur.y += acc0.y + acc1.y;
    *po = cur;
}

// ---------------- launch ----------------
extern "C" void kernel_launch(void* const* d_in, const int* in_sizes, int n_in,
                              void* d_out, int out_size) {
    const int*   edge_index = (const int*)d_in[0];
    const int*   edge_type  = (const int*)d_in[1];
    const float* W1         = (const float*)d_in[2];
    const float* root1      = (const float*)d_in[3];
    const float* b1         = (const float*)d_in[4];
    const float* W2         = (const float*)d_in[5];
    const float* root2      = (const float*)d_in[6];
    const float* b2         = (const float*)d_in[7];
    float*       out        = (float*)d_out;

    cudaFuncSetAttribute(gemm_kernel,
                         cudaFuncAttributeMaxDynamicSharedMemorySize, SM_TOT);

    void* cntp = nullptr;
    cudaGetSymbolAddress(&cntp, g_cnt_rel);
    cudaMemsetAsync(cntp, 0, (size_t)N_NODES * R_REL * sizeof(int), 0);

    count_kernel<<<CNT_BLKS + W2P_BLKS, 256>>>(edge_index, edge_type, W2, root2);
    scan_kernel<<<SCAN_BLKS, 1024>>>();
    permute_kernel<<<CNT_BLKS, 256>>>(edge_index, edge_type);
    agg1_kernel<<<5000, 256>>>(W1, root1, b1);
    gemm_kernel<<<TILES, 256, SM_TOT>>>(b2, out);
    agg2_kernel<<<5000, 256>>>(out);
}

// round 12
// speedup vs baseline: 1.1239x; 1.1239x over previous
#include <cuda_runtime.h>
#include <cuda_bf16.h>
#include <cstdint>

#define N_NODES 40000
#define E_EDGES 640000
#define R_REL   8
#define H_DIM   128
#define C_DIM   64
#define TILES   313          // ceil(40000/128)
#define ROWS_PAD (TILES * 128)
#define CNT_BLKS 2500        // E/256
#define W2P_BLKS 144         // 9*64*64/256
#define SCAN_BLKS 40

// ---------------- scratch (device globals; no allocation) ----------------
__device__ int                g_cnt_rel[N_NODES * R_REL];
__device__ int                g_off[N_NODES + 1];
__device__ int                g_cursor[N_NODES];
__device__ int                g_bsum[SCAN_BLKS];
__device__ unsigned long long g_edge[E_EDGES];           // (scale<<32 | rowid) sorted by dst
__device__ float              g_hall[(size_t)R_REL * N_NODES * C_DIM];
// bf16 split images of h (A operand), row-major [row][k], packed bf16x2 words
__device__ __align__(16) uint32_t g_Ahi[(size_t)ROWS_PAD * 64];
__device__ __align__(16) uint32_t g_Alo[(size_t)ROWS_PAD * 64];
// bf16 split images of W2[r]/root2 (B operand), [r][col][k] packed bf16x2 words
__device__ __align__(16) uint32_t g_Bhi[9 * 64 * 64];
__device__ __align__(16) uint32_t g_Blo[9 * 64 * 64];

// ---------------- helpers ----------------
__device__ __forceinline__ uint32_t pk_hi2(float a, float b, float& la, float& lb) {
    __nv_bfloat16 ha = __float2bfloat16(a);
    __nv_bfloat16 hb = __float2bfloat16(b);
    la = a - __bfloat162float(ha);
    lb = b - __bfloat162float(hb);
    __nv_bfloat162 t(ha, hb);            // ha -> low half
    return *reinterpret_cast<uint32_t*>(&t);
}
__device__ __forceinline__ uint32_t pk2(float a, float b) {
    __nv_bfloat162 t = __floats2bfloat162_rn(a, b);   // a -> low half
    return *reinterpret_cast<uint32_t*>(&t);
}
__device__ __forceinline__ void mma16816(float* c, const uint32_t* a, const uint32_t* b) {
    asm volatile(
        "mma.sync.aligned.m16n8k16.row.col.f32.bf16.bf16.f32 "
        "{%0,%1,%2,%3}, {%4,%5,%6,%7}, {%8,%9}, {%0,%1,%2,%3};"
        : "+f"(c[0]), "+f"(c[1]), "+f"(c[2]), "+f"(c[3])
        : "r"(a[0]), "r"(a[1]), "r"(a[2]), "r"(a[3]), "r"(b[0]), "r"(b[1]));
}
__device__ __forceinline__ int warp_incl_scan(int v, int lane) {
#pragma unroll
    for (int ofs = 1; ofs < 32; ofs <<= 1) {
        int u = __shfl_up_sync(0xffffffffu, v, ofs);
        if (lane >= ofs) v += u;
    }
    return v;
}

// ---------------- count (+ fused w2prep) -------------------------------------
__global__ void count_kernel(const int* __restrict__ edge_index,
                             const int* __restrict__ edge_type,
                             const float* __restrict__ W2,
                             const float* __restrict__ root2) {
    if (blockIdx.x < CNT_BLKS) {
        int e = blockIdx.x * 256 + threadIdx.x;
        if (e < E_EDGES) {
            int dst = edge_index[E_EDGES + e];
            int et  = edge_type[e];
            atomicAdd(&g_cnt_rel[dst * R_REL + et], 1);
        }
    } else {
        // ---- w2prep: W2[r]/root2 -> [r][col][k] bf16 hi/lo ----
        int idx = (blockIdx.x - CNT_BLKS) * 256 + threadIdx.x;
        if (idx >= 9 * 64 * 64) return;
        int r   = idx >> 12;
        int rem = idx & 4095;
        int n   = rem >> 6;
        int k   = (rem & 63) * 2;
        const float* mat = (r < 8) ? (W2 + (size_t)r * H_DIM * C_DIM) : root2;
        float x0 = mat[(size_t)k * C_DIM + n];
        float x1 = mat[(size_t)(k + 1) * C_DIM + n];
        float l0, l1;
        uint32_t hi = pk_hi2(x0, x1, l0, l1);
        uint32_t lo = pk2(l0, l1);
        g_Bhi[idx] = hi;
        g_Blo[idx] = lo;
    }
}

// ---------------- scan pass 1: per-block local exclusive scan ----------------
__global__ __launch_bounds__(1024) void scan1_kernel() {
    const int t = threadIdx.x, lane = t & 31, warp = t >> 5;
    int i = blockIdx.x * 1024 + t;
    int deg = 0;
    if (i < N_NODES) {
        const int4* p = reinterpret_cast<const int4*>(&g_cnt_rel[i * R_REL]);
        int4 a = p[0], c = p[1];
        deg = a.x + a.y + a.z + a.w + c.x + c.y + c.z + c.w;
    }
    int v = warp_incl_scan(deg, lane);
    __shared__ int ws[32];
    if (lane == 31) ws[warp] = v;
    __syncthreads();
    if (warp == 0) ws[lane] = warp_incl_scan(ws[lane], lane);
    __syncthreads();
    int blockExcl = warp ? ws[warp - 1] : 0;
    if (i < N_NODES) g_off[i] = blockExcl + v - deg;   // local exclusive
    if (t == 1023)   g_bsum[blockIdx.x] = blockExcl + v;
}

// ---------------- scan pass 2+3: every block redundantly scans 40 sums -------
__global__ __launch_bounds__(1024) void scan23_kernel() {
    __shared__ int s_pfx;
    const int t = threadIdx.x;
    if (t == 0) {
        int p = 0;
#pragma unroll
        for (int q = 0; q < SCAN_BLKS; q++) {
            if (q == (int)blockIdx.x) break;
            p += g_bsum[q];
        }
        s_pfx = p;
    }
    __syncthreads();
    int i = blockIdx.x * 1024 + t;
    if (i < N_NODES) {
        int o = g_off[i] + s_pfx;
        g_off[i]    = o;
        g_cursor[i] = o;
    }
    if (i == 0) g_off[N_NODES] = E_EDGES;
}

__global__ void permute_kernel(const int* __restrict__ edge_index,
                               const int* __restrict__ edge_type) {
    int e = blockIdx.x * blockDim.x + threadIdx.x;
    if (e >= E_EDGES) return;
    int src = edge_index[e];
    int dst = edge_index[E_EDGES + e];
    int et  = edge_type[e];
    int pos = atomicAdd(&g_cursor[dst], 1);
    int cnt = g_cnt_rel[dst * R_REL + et];
    float sc = 1.0f / (float)cnt;
    unsigned rowid = (unsigned)(et * N_NODES + src);
    g_edge[pos] = ((unsigned long long)__float_as_uint(sc) << 32) | rowid;
}

// ---------------- layer 1 aggregation: warp per node -------------------------
// h[n] = relu(sum scale*W1[rowid,:] + root1[n] + b1); emit bf16 hi/lo rows
__global__ __launch_bounds__(256) void agg1_kernel(const float* __restrict__ W1,
                                                   const float* __restrict__ root1,
                                                   const float* __restrict__ b1) {
    int wid  = threadIdx.x >> 5;
    int lane = threadIdx.x & 31;
    int n = blockIdx.x * 8 + wid;
    if (n >= N_NODES) return;
    int beg = g_off[n], end = g_off[n + 1];

    float4 acc = make_float4(0.f, 0.f, 0.f, 0.f);
    for (int base = beg; base < end; base += 32) {
        int e = base + lane;
        unsigned long long pk = (e < end) ? g_edge[e] : 0ull;
        int m = end - base; if (m > 32) m = 32;
        for (int j = 0; j < m; j++) {
            unsigned long long pj = __shfl_sync(0xffffffffu, pk, j);
            int   rowid = (int)(pj & 0xffffffffu);
            float sc    = __uint_as_float((unsigned)(pj >> 32));
            float4 v = *reinterpret_cast<const float4*>(
                &W1[(size_t)rowid * H_DIM + lane * 4]);
            acc.x = fmaf(sc, v.x, acc.x);
            acc.y = fmaf(sc, v.y, acc.y);
            acc.z = fmaf(sc, v.z, acc.z);
            acc.w = fmaf(sc, v.w, acc.w);
        }
    }
    float4 rt = *reinterpret_cast<const float4*>(&root1[(size_t)n * H_DIM + lane * 4]);
    float4 bb = *reinterpret_cast<const float4*>(&b1[lane * 4]);
    float4 o;
    o.x = fmaxf(acc.x + rt.x + bb.x, 0.f);
    o.y = fmaxf(acc.y + rt.y + bb.y, 0.f);
    o.z = fmaxf(acc.z + rt.z + bb.z, 0.f);
    o.w = fmaxf(acc.w + rt.w + bb.w, 0.f);

    float l0, l1, l2, l3;
    uint32_t h01 = pk_hi2(o.x, o.y, l0, l1);
    uint32_t h23 = pk_hi2(o.z, o.w, l2, l3);
    uint32_t w01 = pk2(l0, l1);
    uint32_t w23 = pk2(l2, l3);
    size_t base = (size_t)n * 64 + lane * 2;
    g_Ahi[base]     = h01;
    g_Ahi[base + 1] = h23;
    g_Alo[base]     = w01;
    g_Alo[base + 1] = w23;
}

// ---------------- bf16-split HMMA batched GEMM -------------------------------
// block = 128-row tile of h, loops r=0..8 with A smem-resident.
// D(128x64 f32) = A_hi*B_hi + A_hi*B_lo + A_lo*B_hi   (each K=128)
#define ROW_B   272
#define A_HI_O  0
#define A_LO_O  34816
#define B_HI_O  69632
#define B_LO_O  87040
#define SM_TOT  104448

__global__ __launch_bounds__(256) void gemm_kernel(const float* __restrict__ bias2,
                                                   float* __restrict__ out) {
    extern __shared__ char sm[];
    const int tid    = threadIdx.x;
    const int lane   = tid & 31;
    const int wid    = tid >> 5;
    const int warp_m = wid >> 1;
    const int warp_n = wid & 1;
    const int g      = lane >> 2;
    const int t      = lane & 3;
    const int tile   = blockIdx.x;

    {
        const float4* sH = reinterpret_cast<const float4*>(g_Ahi + (size_t)tile * 128 * 64);
        const float4* sL = reinterpret_cast<const float4*>(g_Alo + (size_t)tile * 128 * 64);
#pragma unroll
        for (int i = 0; i < 8; i++) {
            int f    = tid + 256 * i;
            int row  = f >> 4;
            int ch   = f & 15;
            *reinterpret_cast<float4*>(sm + A_HI_O + row * ROW_B + ch * 16) = sH[f];
            *reinterpret_cast<float4*>(sm + A_LO_O + row * ROW_B + ch * 16) = sL[f];
        }
    }

    for (int r = 0; r < 9; r++) {
        {
            const float4* sH = reinterpret_cast<const float4*>(g_Bhi + r * 4096);
            const float4* sL = reinterpret_cast<const float4*>(g_Blo + r * 4096);
#pragma unroll
            for (int i = 0; i < 4; i++) {
                int f   = tid + 256 * i;
                int col = f >> 4;
                int ch  = f & 15;
                *reinterpret_cast<float4*>(sm + B_HI_O + col * ROW_B + ch * 16) = sH[f];
                *reinterpret_cast<float4*>(sm + B_LO_O + col * ROW_B + ch * 16) = sL[f];
            }
        }
        __syncthreads();

        float acc[2][4][4];
#pragma unroll
        for (int m = 0; m < 2; m++)
#pragma unroll
            for (int n = 0; n < 4; n++)
#pragma unroll
                for (int c = 0; c < 4; c++) acc[m][n][c] = 0.f;

#pragma unroll
        for (int k8 = 0; k8 < 8; k8++) {
            const int kbyte = (k8 * 16 + t * 2) * 2;
            uint32_t ahi[2][4], alo[2][4];
#pragma unroll
            for (int m = 0; m < 2; m++) {
                const char* p = sm + (warp_m * 32 + m * 16 + g) * ROW_B + kbyte;
                ahi[m][0] = *(const uint32_t*)(p + A_HI_O);
                ahi[m][1] = *(const uint32_t*)(p + A_HI_O + 8 * ROW_B);
                ahi[m][2] = *(const uint32_t*)(p + A_HI_O + 16);
                ahi[m][3] = *(const uint32_t*)(p + A_HI_O + 8 * ROW_B + 16);
                alo[m][0] = *(const uint32_t*)(p + A_LO_O);
                alo[m][1] = *(const uint32_t*)(p + A_LO_O + 8 * ROW_B);
                alo[m][2] = *(const uint32_t*)(p + A_LO_O + 16);
                alo[m][3] = *(const uint32_t*)(p + A_LO_O + 8 * ROW_B + 16);
            }
            uint32_t bhi[4][2], blo[4][2];
#pragma unroll
            for (int n = 0; n < 4; n++) {
                const char* p = sm + (warp_n * 32 + n * 8 + g) * ROW_B + kbyte;
                bhi[n][0] = *(const uint32_t*)(p + B_HI_O);
                bhi[n][1] = *(const uint32_t*)(p + B_HI_O + 16);
                blo[n][0] = *(const uint32_t*)(p + B_LO_O);
                blo[n][1] = *(const uint32_t*)(p + B_LO_O + 16);
            }
#pragma unroll
            for (int m = 0; m < 2; m++)
#pragma unroll
                for (int n = 0; n < 4; n++) {
                    mma16816(acc[m][n], ahi[m], bhi[n]);
                    mma16816(acc[m][n], ahi[m], blo[n]);
                    mma16816(acc[m][n], alo[m], bhi[n]);
                }
        }
        __syncthreads();

#pragma unroll
        for (int m = 0; m < 2; m++) {
            int row0 = tile * 128 + warp_m * 32 + m * 16 + g;
#pragma unroll
            for (int n = 0; n < 4; n++) {
                int col = warp_n * 32 + n * 8 + t * 2;
                if (r < 8) {
                    float* baseP = &g_hall[(size_t)r * N_NODES * C_DIM];
                    if (row0 < N_NODES)
                        *reinterpret_cast<float2*>(&baseP[(size_t)row0 * C_DIM + col]) =
                            make_float2(acc[m][n][0], acc[m][n][1]);
                    if (row0 + 8 < N_NODES)
                        *reinterpret_cast<float2*>(&baseP[(size_t)(row0 + 8) * C_DIM + col]) =
                            make_float2(acc[m][n][2], acc[m][n][3]);
                } else {
                    float2 bb = *reinterpret_cast<const float2*>(&bias2[col]);
                    if (row0 < N_NODES)
                        *reinterpret_cast<float2*>(&out[(size_t)row0 * C_DIM + col]) =
                            make_float2(acc[m][n][0] + bb.x, acc[m][n][1] + bb.y);
                    if (row0 + 8 < N_NODES)
                        *reinterpret_cast<float2*>(&out[(size_t)(row0 + 8) * C_DIM + col]) =
                            make_float2(acc[m][n][2] + bb.x, acc[m][n][3] + bb.y);
                }
            }
        }
    }
}

// ---------------- layer 2 aggregation: warp per node -------------------------
__global__ __launch_bounds__(256) void agg2_kernel(float* __restrict__ out) {
    int wid  = threadIdx.x >> 5;
    int lane = threadIdx.x & 31;
    int n = blockIdx.x * 8 + wid;
    if (n >= N_NODES) return;
    int beg = g_off[n], end = g_off[n + 1];
    if (beg == end) return;

    float2 acc = make_float2(0.f, 0.f);
    for (int base = beg; base < end; base += 32) {
        int e = base + lane;
        unsigned long long pk = (e < end) ? g_edge[e] : 0ull;
        int m = end - base; if (m > 32) m = 32;
        for (int j = 0; j < m; j++) {
            unsigned long long pj = __shfl_sync(0xffffffffu, pk, j);
            int   rowid = (int)(pj & 0xffffffffu);
            float sc    = __uint_as_float((unsigned)(pj >> 32));
            float2 v = *reinterpret_cast<const float2*>(
                &g_hall[(size_t)rowid * C_DIM + lane * 2]);
            acc.x = fmaf(sc, v.x, acc.x);
            acc.y = fmaf(sc, v.y, acc.y);
        }
    }
    float2* po = reinterpret_cast<float2*>(&out[(size_t)n * C_DIM + lane * 2]);
    float2 cur = *po;
    cur.x += acc.x;
    cur.y += acc.y;
    *po = cur;
}

// ---------------- launch ----------------
extern "C" void kernel_launch(void* const* d_in, const int* in_sizes, int n_in,
                              void* d_out, int out_size) {
    const int*   edge_index = (const int*)d_in[0];
    const int*   edge_type  = (const int*)d_in[1];
    const float* W1         = (const float*)d_in[2];
    const float* root1      = (const float*)d_in[3];
    const float* b1         = (const float*)d_in[4];
    const float* W2         = (const float*)d_in[5];
    const float* root2      = (const float*)d_in[6];
    const float* b2         = (const float*)d_in[7];
    float*       out        = (float*)d_out;

    cudaFuncSetAttribute(gemm_kernel,
                         cudaFuncAttributeMaxDynamicSharedMemorySize, SM_TOT);

    void* cntp = nullptr;
    cudaGetSymbolAddress(&cntp, g_cnt_rel);
    cudaMemsetAsync(cntp, 0, (size_t)N_NODES * R_REL * sizeof(int), 0);

    count_kernel<<<CNT_BLKS + W2P_BLKS, 256>>>(edge_index, edge_type, W2, root2);
    scan1_kernel<<<SCAN_BLKS, 1024>>>();
    scan23_kernel<<<SCAN_BLKS, 1024>>>();
    permute_kernel<<<CNT_BLKS, 256>>>(edge_index, edge_type);
    agg1_kernel<<<5000, 256>>>(W1, root1, b1);
    gemm_kernel<<<TILES, 256, SM_TOT>>>(b2, out);
    agg2_kernel<<<5000, 256>>>(out);
}